// round 17
// baseline (speedup 1.0000x reference)
#include <cuda_runtime.h>
#include <cstdint>

#define HW   (1024 * 1024)
#define NB   4
#define NC   3
#define MH   25
#define NDEPTH 6
#define RW   14            // row stride in u64: 13 c-pair weights + 1 pad

typedef unsigned long long u64;

#define MLOG2E  (-1.442695040888963407f) // -log2(e), folded into w_out for sigmoid

// ---------- packed f32x2 helpers ----------
__device__ __forceinline__ u64 pack2(float lo, float hi) {
    u64 r; asm("mov.b64 %0, {%1, %2};" : "=l"(r) : "f"(lo), "f"(hi)); return r;
}
__device__ __forceinline__ void unpack2(u64 v, float& lo, float& hi) {
    asm("mov.b64 {%0, %1}, %2;" : "=f"(lo), "=f"(hi) : "l"(v));
}
__device__ __forceinline__ u64 fma2_(u64 a, u64 b, u64 c) {
    u64 d; asm("fma.rn.f32x2 %0, %1, %2, %3;" : "=l"(d) : "l"(a), "l"(b), "l"(c)); return d;
}
__device__ __forceinline__ u64 mul2_(u64 a, u64 b) {
    u64 d; asm("mul.rn.f32x2 %0, %1, %2;" : "=l"(d) : "l"(a), "l"(b)); return d;
}
__device__ __forceinline__ float ex2f(float a) {
    float r; asm("ex2.approx.f32 %0, %1;" : "=f"(r) : "f"(a)); return r;
}
__device__ __forceinline__ float rcpf(float a) {
    float r; asm("rcp.approx.f32 %0, %1;" : "=f"(r) : "f"(a)); return r;
}
__device__ __forceinline__ float tanhf_(float a) {
    float r; asm("tanh.approx.f32 %0, %1;" : "=f"(r) : "f"(a)); return r;
}
__device__ __forceinline__ float hadd2(u64 v) {
    float lo, hi; unpack2(v, lo, hi); return lo + hi;
}
// sigmoid on PRE-SCALED input zs = -log2(e)*z
__device__ __forceinline__ float sigms(float zs) {
    return rcpf(1.0f + ex2f(zs));
}

// One hidden layer 25->25 for 2 pixels: output-major, c-pair packed weights,
// horizontal add + immediate (distributed) MUFU.TANH. h arrays: 13 u64/px,
// lane = {h[2q], h[2q+1]}; pair 12 = {h24, finite}; weight u64 12 = {w24, 0}.
__device__ __forceinline__ void layer25(const u64* __restrict__ wl,
                                        const u64* hA, const u64* hB,
                                        u64* nhA, u64* nhB) {
#pragma unroll
    for (int j = 0; j < 12; j++) {            // outputs o = 2j, 2j+1
        const u64* r0 = wl + (2 * j) * RW;
        const u64* r1 = wl + (2 * j + 1) * RW;
        u64 a0, a1, b0, b1;
        {
            ulonglong2 w0 = *(const ulonglong2*)(r0);
            ulonglong2 w1 = *(const ulonglong2*)(r1);
            a0 = mul2_(w0.x, hA[0]);  b0 = mul2_(w0.x, hB[0]);
            a1 = mul2_(w1.x, hA[0]);  b1 = mul2_(w1.x, hB[0]);
            a0 = fma2_(w0.y, hA[1], a0);  b0 = fma2_(w0.y, hB[1], b0);
            a1 = fma2_(w1.y, hA[1], a1);  b1 = fma2_(w1.y, hB[1], b1);
        }
#pragma unroll
        for (int q = 1; q < 6; q++) {
            ulonglong2 w0 = *(const ulonglong2*)(r0 + 2 * q);
            ulonglong2 w1 = *(const ulonglong2*)(r1 + 2 * q);
            a0 = fma2_(w0.x, hA[2 * q], a0);      b0 = fma2_(w0.x, hB[2 * q], b0);
            a1 = fma2_(w1.x, hA[2 * q], a1);      b1 = fma2_(w1.x, hB[2 * q], b1);
            a0 = fma2_(w0.y, hA[2 * q + 1], a0);  b0 = fma2_(w0.y, hB[2 * q + 1], b0);
            a1 = fma2_(w1.y, hA[2 * q + 1], a1);  b1 = fma2_(w1.y, hB[2 * q + 1], b1);
        }
        {
            u64 w0 = r0[12], w1 = r1[12];     // {w24, 0}: pad lane multiplies to 0
            a0 = fma2_(w0, hA[12], a0);  b0 = fma2_(w0, hB[12], b0);
            a1 = fma2_(w1, hA[12], a1);  b1 = fma2_(w1, hB[12], b1);
        }
        nhA[j] = pack2(tanhf_(hadd2(a0)), tanhf_(hadd2(a1)));
        nhB[j] = pack2(tanhf_(hadd2(b0)), tanhf_(hadd2(b1)));
    }
    {   // output o = 24 (single row)
        const u64* r0 = wl + 24 * RW;
        u64 a0, b0;
        {
            ulonglong2 w0 = *(const ulonglong2*)(r0);
            a0 = mul2_(w0.x, hA[0]);      b0 = mul2_(w0.x, hB[0]);
            a0 = fma2_(w0.y, hA[1], a0);  b0 = fma2_(w0.y, hB[1], b0);
        }
#pragma unroll
        for (int q = 1; q < 6; q++) {
            ulonglong2 w0 = *(const ulonglong2*)(r0 + 2 * q);
            a0 = fma2_(w0.x, hA[2 * q], a0);      b0 = fma2_(w0.x, hB[2 * q], b0);
            a0 = fma2_(w0.y, hA[2 * q + 1], a0);  b0 = fma2_(w0.y, hB[2 * q + 1], b0);
        }
        u64 w0 = r0[12];
        a0 = fma2_(w0, hA[12], a0);  b0 = fma2_(w0, hB[12], b0);
        nhA[12] = pack2(tanhf_(hadd2(a0)), 0.0f);   // pad lane finite 0
        nhB[12] = pack2(tanhf_(hadd2(b0)), 0.0f);
    }
}

__global__ __launch_bounds__(128, 4)
void simplenet_kernel(const float* __restrict__ x,
                      const float* __restrict__ w_in,
                      const float* __restrict__ ws,
                      const float* __restrict__ w_out,
                      float* __restrict__ out) {
    // Hidden weights: row-major per output o, c-pair packed {w[o][2q], w[o][2q+1]}
    // (RAW — tanh.approx takes unscaled z). Row stride 14 u64 (112B, 16B-aligned).
    __shared__ __align__(16) u64   s_mid[NDEPTH][MH][RW];
    __shared__ __align__(16) float s_win[MH][4];           // input layer, raw
    __shared__ __align__(16) u64   s_wout[NC][RW];         // c-pair packed, * -log2e

    const int tid = threadIdx.x;

    for (int t = tid; t < NDEPTH * MH * RW; t += 128) {
        int l = t / (MH * RW);
        int r = t - l * (MH * RW);
        int o = r / RW;
        int k = r - o * RW;
        u64 v = 0ull;
        if (k < 13) {
            int c0 = 2 * k, c1 = 2 * k + 1;
            float lo = ws[(l * MH + o) * MH + c0];
            float hi = (c1 < MH) ? ws[(l * MH + o) * MH + c1] : 0.0f;
            v = pack2(lo, hi);
        }
        s_mid[l][o][k] = v;
    }
    for (int t = tid; t < MH * 4; t += 128) {
        int o = t >> 2, c = t & 3;
        s_win[o][c] = (c < NC) ? w_in[o * NC + c] : 0.0f;
    }
    for (int t = tid; t < NC * RW; t += 128) {
        int o = t / RW, k = t - (t / RW) * RW;
        u64 v = 0ull;
        if (k < 13) {
            int c0 = 2 * k, c1 = 2 * k + 1;
            float lo = w_out[o * MH + c0] * MLOG2E;
            float hi = (c1 < MH) ? w_out[o * MH + c1] * MLOG2E : 0.0f;
            v = pack2(lo, hi);
        }
        s_wout[o][k] = v;
    }
    __syncthreads();

    unsigned gp  = blockIdx.x * 128u + (unsigned)tid;   // pixel-pair index
    unsigned idx = gp * 2u;                             // grid covers domain exactly
    unsigned b   = idx >> 20;
    unsigned rem = idx & (HW - 1);

    const float* px = x + (size_t)b * (NC * HW) + rem;
    float2 v0 = *(const float2*)(px);                 // (pixA, pixB) channel 0
    float2 v1 = *(const float2*)(px + HW);
    float2 v2 = *(const float2*)(px + 2 * HW);

    u64 hA[13], hB[13];     // {h2q, h2q+1} activation pairs per pixel
    u64 nA[13], nB[13];     // double buffer

    // ---- input layer: 3 -> 25 scalar, tanh distributed ----
#pragma unroll
    for (int j = 0; j < 12; j++) {
        int o0 = 2 * j, o1 = 2 * j + 1;
        float zA0 = fmaf(s_win[o0][2], v2.x, fmaf(s_win[o0][1], v1.x, s_win[o0][0] * v0.x));
        float zA1 = fmaf(s_win[o1][2], v2.x, fmaf(s_win[o1][1], v1.x, s_win[o1][0] * v0.x));
        float zB0 = fmaf(s_win[o0][2], v2.y, fmaf(s_win[o0][1], v1.y, s_win[o0][0] * v0.y));
        float zB1 = fmaf(s_win[o1][2], v2.y, fmaf(s_win[o1][1], v1.y, s_win[o1][0] * v0.y));
        hA[j] = pack2(tanhf_(zA0), tanhf_(zA1));
        hB[j] = pack2(tanhf_(zB0), tanhf_(zB1));
    }
    {
        float zA = fmaf(s_win[24][2], v2.x, fmaf(s_win[24][1], v1.x, s_win[24][0] * v0.x));
        float zB = fmaf(s_win[24][2], v2.y, fmaf(s_win[24][1], v1.y, s_win[24][0] * v0.y));
        hA[12] = pack2(tanhf_(zA), 0.0f);
        hB[12] = pack2(tanhf_(zB), 0.0f);
    }

    // ---- 6 hidden layers: double-buffered, 2 per outer iteration ----
#pragma unroll 1
    for (int it = 0; it < NDEPTH / 2; it++) {
        layer25(&s_mid[2 * it][0][0],     hA, hB, nA, nB);
        layer25(&s_mid[2 * it + 1][0][0], nA, nB, hA, hB);
    }

    // ---- output layer: 25 -> 3 (weights pre-scaled -log2e), sigmoid ----
    float* po = out + (size_t)b * (NC * HW) + rem;
#pragma unroll
    for (int o = 0; o < NC; o++) {
        const u64* r0 = &s_wout[o][0];
        u64 a0, b0;
        {
            ulonglong2 w0 = *(const ulonglong2*)(r0);
            a0 = mul2_(w0.x, hA[0]);      b0 = mul2_(w0.x, hB[0]);
            a0 = fma2_(w0.y, hA[1], a0);  b0 = fma2_(w0.y, hB[1], b0);
        }
#pragma unroll
        for (int q = 1; q < 6; q++) {
            ulonglong2 w0 = *(const ulonglong2*)(r0 + 2 * q);
            a0 = fma2_(w0.x, hA[2 * q], a0);      b0 = fma2_(w0.x, hB[2 * q], b0);
            a0 = fma2_(w0.y, hA[2 * q + 1], a0);  b0 = fma2_(w0.y, hB[2 * q + 1], b0);
        }
        u64 w0 = r0[12];
        a0 = fma2_(w0, hA[12], a0);  b0 = fma2_(w0, hB[12], b0);
        *(float2*)(po + o * HW) = make_float2(sigms(hadd2(a0)), sigms(hadd2(b0)));
    }
}

extern "C" void kernel_launch(void* const* d_in, const int* in_sizes, int n_in,
                              void* d_out, int out_size) {
    const float* x     = (const float*)d_in[0];
    const float* w_in  = (const float*)d_in[1];
    const float* ws    = (const float*)d_in[2];
    const float* w_out = (const float*)d_in[3];
    float* out = (float*)d_out;

    const int pairs = NB * HW / 2;            // 2,097,152
    dim3 block(128);
    dim3 grid(pairs / 128);                   // 16384
    simplenet_kernel<<<grid, block>>>(x, w_in, ws, w_out, out);
}